// round 14
// baseline (speedup 1.0000x reference)
#include <cuda_runtime.h>
#include <cuda_fp16.h>
#include <mma.h>
#include <cstdint>

using namespace nvcuda;

// ----------------------------------------------------------------------------
// out[64,14336](fp32) = (x[64,4096]*xs) @ (w[14336,4096]*ws)^T
// int32 inputs (harness promotes int8->int32), fp32 scales/output.
// R14: software-pipelined iteration. Double-buffered fp16 tiles; compute of
// tile[i-1] runs BEFORE wait_group for stage i (DRAM wait overlapped by own
// compute); ONE __syncthreads per iteration. W = 2-stage cp.async raw int32;
// X = register prefetch. Split-K x4 (448 CTAs, 3/SM). atomicAdd epilogue.
// ----------------------------------------------------------------------------

#define M_TOK   64
#define KDIM    4096
#define NOUT    14336
#define TILE_N  128
#define SPLITS  4
#define KR      (KDIM / SPLITS)            // 1024 per split
#define KC      32                         // K ints per iteration
#define ITERS   (KR / KC)                  // 32
#define RAW_ROW 144                        // bytes per raw W row (128 + 16 pad)
#define W_RAW   (TILE_N * RAW_ROW)         // 18432 per stage
#define WSTRIDE 40                         // halves per fp16 tile row
#define WT_BYTES (TILE_N * WSTRIDE * 2)    // 10240
#define XT_BYTES (M_TOK * WSTRIDE * 2)     // 5120
#define TILE_PAIR (WT_BYTES + XT_BYTES)    // 15360
#define TILES_OFF (2 * W_RAW)              // 36864
#define SMEM_TOTAL (TILES_OFF + 2 * TILE_PAIR)   // 67584 (x3 = 203KB/SM)
#define OUT_ELEMS ((long)M_TOK * NOUT)     // 917504

__global__ void zero_kernel(float* out, long n) {
    long i = (long)blockIdx.x * blockDim.x + threadIdx.x;
    if (i < n) out[i] = 0.0f;
}

__device__ __forceinline__ uint32_t smem_u32(const void* p) {
    uint32_t a;
    asm("{ .reg .u64 t; cvta.to.shared.u64 t, %1; cvt.u32.u64 %0, t; }" : "=r"(a) : "l"(p));
    return a;
}

__device__ __forceinline__ void cp_async16(uint32_t smem_dst, const void* gmem_src) {
    asm volatile("cp.async.cg.shared.global [%0], [%1], 16;"
                 :: "r"(smem_dst), "l"(gmem_src) : "memory");
}

// 4 int32 -> 4 fp16 packed (exact for small ints)
__device__ __forceinline__ uint2 cvt4(uint4 v) {
    __half2 lo = __halves2half2(__int2half_rn((int)v.x), __int2half_rn((int)v.y));
    __half2 hi = __halves2half2(__int2half_rn((int)v.z), __int2half_rn((int)v.w));
    uint2 r;
    r.x = *reinterpret_cast<uint32_t*>(&lo);
    r.y = *reinterpret_cast<uint32_t*>(&hi);
    return r;
}

__global__ __launch_bounds__(256, 3) void Model_89704686944640_kernel(
    const int* __restrict__ w, const int* __restrict__ x,
    const float* __restrict__ s0, const float* __restrict__ s1,
    float* __restrict__ out) {
    extern __shared__ char smem[];
    const uint32_t raw_base = smem_u32(smem);

    const int tid = threadIdx.x;
    const int wid = tid >> 5;
    const int lane = tid & 31;
    const int fg = wid & 3;                    // feature group (4 x 32)
    const int tg = wid >> 2;                   // token group (2 x 32)
    const int tile = blockIdx.x;
    const int split = blockIdx.y;
    const long wbase = (long)tile * TILE_N * KDIM;
    const int kbase0 = split * KR;

    // W: 1024 16B-chunks/iter -> 4/thr ; X: 512 -> 2/thr
    const int ch = tid & 7;
    const int ch4 = ch * 4;
    const int wrow[4] = { (tid + 0) >> 3, (tid + 256) >> 3,
                          (tid + 512) >> 3, (tid + 768) >> 3 };
    const int xrow[2] = { (tid + 0) >> 3, (tid + 256) >> 3 };

    wmma::fragment<wmma::accumulator, 16, 16, 16, float> c00, c01, c10, c11;
    wmma::fill_fragment(c00, 0.0f); wmma::fill_fragment(c01, 0.0f);
    wmma::fill_fragment(c10, 0.0f); wmma::fill_fragment(c11, 0.0f);

    // ---- prologue: W stages 0,1 via cp.async; X iter 0 into regs ----
    uint4 xr[2];
#pragma unroll
    for (int r = 0; r < 2; r++)
        xr[r] = *reinterpret_cast<const uint4*>(x + (long)xrow[r] * KDIM + kbase0 + ch4);
#pragma unroll
    for (int st = 0; st < 2; st++) {
        const int koff = kbase0 + st * KC;
        const uint32_t sraw = raw_base + st * W_RAW;
#pragma unroll
        for (int r = 0; r < 4; r++)
            cp_async16(sraw + wrow[r] * RAW_ROW + ch * 16,
                       w + wbase + (long)wrow[r] * KDIM + koff + ch4);
        asm volatile("cp.async.commit_group;" ::: "memory");
    }

    // ---- pipelined main loop: compute lags converts by one iteration ----
    for (int i = 0; i <= ITERS; i++) {
        __syncthreads();   // orders iter i-1 converts before iter i compute,
                           // and iter i-1 computes before iter i tile writes

        if (i > 0) {       // compute tile pair (i-1)&1 (overlaps wait below)
            const int b = (i - 1) & 1;
            const __half* wt = reinterpret_cast<const __half*>(smem + TILES_OFF + b * TILE_PAIR);
            const __half* xt = reinterpret_cast<const __half*>(smem + TILES_OFF + b * TILE_PAIR + WT_BYTES);
#pragma unroll
            for (int ks = 0; ks < 2; ks++) {
                wmma::fragment<wmma::matrix_b, 16, 16, 16, __half, wmma::col_major> b0, b1;
                wmma::load_matrix_sync(b0, wt + (fg * 32) * WSTRIDE + ks * 16, WSTRIDE);
                wmma::load_matrix_sync(b1, wt + (fg * 32 + 16) * WSTRIDE + ks * 16, WSTRIDE);
                wmma::fragment<wmma::matrix_a, 16, 16, 16, __half, wmma::row_major> a0, a1;
                wmma::load_matrix_sync(a0, xt + (tg * 32) * WSTRIDE + ks * 16, WSTRIDE);
                wmma::load_matrix_sync(a1, xt + (tg * 32 + 16) * WSTRIDE + ks * 16, WSTRIDE);
                wmma::mma_sync(c00, a0, b0, c00);
                wmma::mma_sync(c01, a0, b1, c01);
                wmma::mma_sync(c10, a1, b0, c10);
                wmma::mma_sync(c11, a1, b1, c11);
            }
        }

        if (i < ITERS) {
            asm volatile("cp.async.wait_group 1;" ::: "memory");  // stage i&1 arrived
            const int b = i & 1;
            char* rawS = smem + b * W_RAW;
            __half* wt = reinterpret_cast<__half*>(smem + TILES_OFF + b * TILE_PAIR);
            __half* xt = reinterpret_cast<__half*>(smem + TILES_OFF + b * TILE_PAIR + WT_BYTES);

            // convert W raw -> fp16 tile (self-written chunks only)
#pragma unroll
            for (int r = 0; r < 4; r++) {
                uint4 v = *reinterpret_cast<const uint4*>(rawS + wrow[r] * RAW_ROW + ch * 16);
                *reinterpret_cast<uint2*>(&wt[wrow[r] * WSTRIDE + ch4]) = cvt4(v);
            }
            // convert X regs -> fp16 tile
#pragma unroll
            for (int r = 0; r < 2; r++)
                *reinterpret_cast<uint2*>(&xt[xrow[r] * WSTRIDE + ch4]) = cvt4(xr[r]);

            // prefetch X regs for iter i+1 (slack = one full iteration)
            if (i + 1 < ITERS) {
                const int koff = kbase0 + (i + 1) * KC;
#pragma unroll
                for (int r = 0; r < 2; r++)
                    xr[r] = *reinterpret_cast<const uint4*>(x + (long)xrow[r] * KDIM + koff + ch4);
            }
            // refill W raw stage b for iter i+2 (safe: this thread already read it)
            if (i + 2 < ITERS) {
                const int koff = kbase0 + (i + 2) * KC;
                const uint32_t sraw = raw_base + b * W_RAW;
#pragma unroll
                for (int r = 0; r < 4; r++)
                    cp_async16(sraw + wrow[r] * RAW_ROW + ch * 16,
                               w + wbase + (long)wrow[r] * KDIM + koff + ch4);
            }
            asm volatile("cp.async.commit_group;" ::: "memory");  // one group per iter
        }
    }

    // ---- epilogue: scale, stage per-warp, atomicAdd (exact integer adds) ----
    float sc = (s0 ? s0[0] : 1.0f) * (s1 ? s1[0] : 1.0f);
#pragma unroll
    for (int i = 0; i < c00.num_elements; i++) {
        c00.x[i] *= sc; c01.x[i] *= sc; c10.x[i] *= sc; c11.x[i] *= sc;
    }
    __syncthreads();   // done with tiles; reuse smem as fp32 scratch
    float* scr = reinterpret_cast<float*>(smem) + wid * 256;   // 1KB per warp
    const long colbase = (long)tile * TILE_N + fg * 32;
    const int er = lane >> 1;            // 0..15
    const int ec = (lane & 1) * 8;       // 0 or 8

    wmma::fragment<wmma::accumulator, 16, 16, 16, float>* frag[4] = {&c00, &c01, &c10, &c11};
#pragma unroll
    for (int f = 0; f < 4; f++) {
        wmma::store_matrix_sync(scr, *frag[f], 16, wmma::mem_row_major);
        __syncwarp();
        const long tok = tg * 32 + (f >> 1) * 16 + er;
        float* dst = out + tok * NOUT + colbase + (f & 1) * 16 + ec;
#pragma unroll
        for (int j = 0; j < 8; j++)
            atomicAdd(dst + j, scr[er * 16 + ec + j]);
        __syncwarp();
    }
}

extern "C" void kernel_launch(void* const* d_in, const int* in_sizes, int n_in,
                              void* d_out, int out_size) {
    const int* w_q = nullptr;
    const int* x_q = nullptr;
    const float* s0 = nullptr;
    const float* s1 = nullptr;
    for (int i = 0; i < n_in; i++) {
        long n = in_sizes[i];
        if (n == (long)NOUT * KDIM) w_q = (const int*)d_in[i];
        else if (n == (long)M_TOK * KDIM) x_q = (const int*)d_in[i];
        else if (n <= 1) { if (!s0) s0 = (const float*)d_in[i]; else if (!s1) s1 = (const float*)d_in[i]; }
    }
    if (!x_q && n_in > 0) x_q = (const int*)d_in[0];
    if (!s0 && n_in > 1) s0 = (const float*)d_in[1];
    if (!w_q && n_in > 2) w_q = (const int*)d_in[2];
    if (!s1 && n_in > 3) s1 = (const float*)d_in[3];
    float* out = (float*)d_out;

    // zero the whole output (atomic accumulation target; graph-replay safe)
    long n = (long)out_size;
    zero_kernel<<<(int)((n + 255) / 256), 256>>>(out, n);

    cudaFuncSetAttribute(Model_89704686944640_kernel,
                         cudaFuncAttributeMaxDynamicSharedMemorySize, SMEM_TOTAL);
    dim3 grid(NOUT / TILE_N, SPLITS);
    Model_89704686944640_kernel<<<grid, 256, SMEM_TOTAL>>>(w_q, x_q, s0, s1, out);
}